// round 10
// baseline (speedup 1.0000x reference)
#include <cuda_runtime.h>
#include <cstdint>

// MultiStepIFNode: T=16 integrate-and-fire over (16, 32, 128, 32, 32) fp32.
// Per neuron: v += x[t]; spike = (v >= 1); v -= spike.
//
// ===================== CONVERGED FINAL KERNEL =====================
// Pure HBM streaming at the provable traffic minimum: 256 MiB in +
// 256 MiB out (measured BW x time == 2x tensor size; zero wasted bytes).
// Best measured: 81.98us dur_us / ~77us kernel @ 6.4 TB/s.
//
// Closed experiment matrix (R1-R9), two-sided:
//   supply: occupancy 21-88%, per-thread MLP 2-16, persistent vs waved
//           grid, block 128/256          -> all within 2% (scheduler is
//                                           request-saturated everywhere)
//   drain:  store default/__stcs/__stwt -> __stcs best; __stwt -2.5%
//           (eager write-through fragments the write stream)
//   losers: persistent 444-CTA grid -10% (starves chip-level MLP)
// Every sane config: 6.26-6.41 TB/s = ~79% of 8 TB/s spec. Residue is
// DRAM bus turnaround/refresh on a bidirectional stream — not SASS-
// addressable. TMA cannot beat this: LTS cap is path-independent
// (LDG.cv == TMA, B300_MICROARCH).
//
// Structure: one thread owns 4 consecutive neurons (float4). Front-batch
// all 16 timestep loads (contiguous read burst, 16 outstanding
// LDG.E.128 evict-first), run the v-recurrence in registers, emit 16
// STG.E.128 evict-first. Fully coalesced; grid exactly covers n4
// (1,048,576 = 4096 x 256) so no bounds guard.

static constexpr int T_STEPS = 16;

__global__ __launch_bounds__(256, 2) void if_multistep_kernel(
    const float4* __restrict__ x,   // T * n4 float4s
    float4* __restrict__ out,       // T * n4 float4s
    int n4)                         // float4s per timestep (N/4)
{
    const int i = blockIdx.x * blockDim.x + threadIdx.x;

    // Front-batch all 16 loads before any store issues.
    float4 xt[T_STEPS];
    #pragma unroll
    for (int t = 0; t < T_STEPS; t++) {
        xt[t] = __ldcs(&x[(size_t)t * n4 + i]);
    }

    float vx = 0.f, vy = 0.f, vz = 0.f, vw = 0.f;

    #pragma unroll
    for (int t = 0; t < T_STEPS; t++) {
        vx += xt[t].x;
        vy += xt[t].y;
        vz += xt[t].z;
        vw += xt[t].w;

        float4 s;
        s.x = (vx >= 1.0f) ? 1.0f : 0.0f;
        s.y = (vy >= 1.0f) ? 1.0f : 0.0f;
        s.z = (vz >= 1.0f) ? 1.0f : 0.0f;
        s.w = (vw >= 1.0f) ? 1.0f : 0.0f;

        vx -= s.x;
        vy -= s.y;
        vz -= s.z;
        vw -= s.w;

        __stcs(&out[(size_t)t * n4 + i], s);
    }
}

extern "C" void kernel_launch(void* const* d_in, const int* in_sizes, int n_in,
                              void* d_out, int out_size)
{
    const float4* x = (const float4*)d_in[0];
    float4* out = (float4*)d_out;

    int n_per_step = out_size / T_STEPS;   // 4,194,304
    int n4 = n_per_step / 4;               // 1,048,576 (exact multiple of 4096*256)

    const int threads = 256;
    int blocks = n4 / threads;             // 4096, exact
    if_multistep_kernel<<<blocks, threads>>>(x, out, n4);
}

// round 11
// speedup vs baseline: 1.0070x; 1.0070x over previous
#include <cuda_runtime.h>
#include <cstdint>

// MultiStepIFNode: T=16 integrate-and-fire over (16, 32, 128, 32, 32) fp32.
// Per neuron: v += x[t]; spike = (v >= 1); v -= spike.
//
// ===================== CONVERGED FINAL KERNEL =====================
// Pure HBM streaming at the provable traffic minimum: 256 MiB in +
// 256 MiB out (measured bytes == logical minimum; zero waste).
// Measured across 6 reproductions: 81.98-82.69us dur_us, ~76-77us
// kernel, 6.26-6.41 TB/s (~79-80% of 8 TB/s spec).
//
// Closed experiment matrix (R1-R10), two-sided:
//   supply: occupancy 21-88%, per-thread MLP 2-16, persistent vs waved
//           grid, block 128/256          -> all within 2%
//   drain:  store default/__stcs/__stwt -> __stcs best; __stwt -2.5%
//   losers: persistent 444-CTA grid -10% (starves chip-level MLP)
// Residue (~20% DRAM-idle) is bidirectional-stream bus turnaround /
// refresh — not SASS-addressable. TMA cannot beat this path: the
// LTS/DRAM cap is path-independent (LDG.cv == TMA, B300_MICROARCH).
//
// Structure: one thread owns 4 consecutive neurons (float4). Front-batch
// all 16 timestep loads (contiguous read burst, 16 outstanding
// LDG.E.128 evict-first), run the v-recurrence in registers, emit 16
// STG.E.128 evict-first. Fully coalesced; grid exactly covers n4
// (1,048,576 = 4096 x 256) so no bounds guard.

static constexpr int T_STEPS = 16;

__global__ __launch_bounds__(256, 2) void if_multistep_kernel(
    const float4* __restrict__ x,   // T * n4 float4s
    float4* __restrict__ out,       // T * n4 float4s
    int n4)                         // float4s per timestep (N/4)
{
    const int i = blockIdx.x * blockDim.x + threadIdx.x;

    // Front-batch all 16 loads before any store issues.
    float4 xt[T_STEPS];
    #pragma unroll
    for (int t = 0; t < T_STEPS; t++) {
        xt[t] = __ldcs(&x[(size_t)t * n4 + i]);
    }

    float vx = 0.f, vy = 0.f, vz = 0.f, vw = 0.f;

    #pragma unroll
    for (int t = 0; t < T_STEPS; t++) {
        vx += xt[t].x;
        vy += xt[t].y;
        vz += xt[t].z;
        vw += xt[t].w;

        float4 s;
        s.x = (vx >= 1.0f) ? 1.0f : 0.0f;
        s.y = (vy >= 1.0f) ? 1.0f : 0.0f;
        s.z = (vz >= 1.0f) ? 1.0f : 0.0f;
        s.w = (vw >= 1.0f) ? 1.0f : 0.0f;

        vx -= s.x;
        vy -= s.y;
        vz -= s.z;
        vw -= s.w;

        __stcs(&out[(size_t)t * n4 + i], s);
    }
}

extern "C" void kernel_launch(void* const* d_in, const int* in_sizes, int n_in,
                              void* d_out, int out_size)
{
    const float4* x = (const float4*)d_in[0];
    float4* out = (float4*)d_out;

    int n_per_step = out_size / T_STEPS;   // 4,194,304
    int n4 = n_per_step / 4;               // 1,048,576 (exact multiple of 4096*256)

    const int threads = 256;
    int blocks = n4 / threads;             // 4096, exact
    if_multistep_kernel<<<blocks, threads>>>(x, out, n4);
}